// round 13
// baseline (speedup 1.0000x reference)
#include <cuda_runtime.h>
#include <cuda_bf16.h>
#include <cstdint>

#define B_    4
#define C_    64
#define T_    80
#define S_    2304
#define N_    128
#define NT_   10
#define TOUT_ 71
#define F_    320
#define KC    64
#define NCHUNK 36                 // chunks per tile
#define NTILE  160                // M128 tiles
#define GRID_G 148
#define NLONG  136                // CTAs with 39 chunks; rest 38

// ---------------- device scratch -------------------------------------------
__device__ __align__(16) __nv_bfloat16 g_wsT[N_*S_];    // [n][s] bf16
__device__ float g_Rpart[NTILE*2*2*N_];                  // [tile][ord][fl][n]

// ---------------- helpers ---------------------------------------------------
__device__ __forceinline__ uint32_t smem_u32(const void* p) {
    uint32_t a;
    asm("{ .reg .u64 t; cvta.to.shared.u64 t, %1; cvt.u32.u64 %0, t; }" : "=r"(a) : "l"(p));
    return a;
}
__device__ __forceinline__ uint32_t pack_bf16(float lo, float hi) {
    uint32_t r;
    asm("cvt.rn.bf16x2.f32 %0, %1, %2;" : "=r"(r) : "f"(hi), "f"(lo));
    return r;
}
__device__ __forceinline__ void cp16(uint32_t dst, const void* src) {
    asm volatile("cp.async.cg.shared.global [%0], [%1], 16;" :: "r"(dst), "l"(src) : "memory");
}
#define CP_COMMIT() asm volatile("cp.async.commit_group;" ::: "memory")
#define CP_WAIT1()  asm volatile("cp.async.wait_group 1;" ::: "memory")

__device__ __forceinline__ void mma_bf16(float* d, const uint32_t* a, const uint32_t* b) {
    asm volatile("mma.sync.aligned.m16n8k16.row.col.f32.bf16.bf16.f32 "
        "{%0,%1,%2,%3}, {%4,%5,%6,%7}, {%8,%9}, {%0,%1,%2,%3};"
        : "+f"(d[0]), "+f"(d[1]), "+f"(d[2]), "+f"(d[3])
        : "r"(a[0]), "r"(a[1]), "r"(a[2]), "r"(a[3]), "r"(b[0]), "r"(b[1]));
}
__device__ __forceinline__ void ldmx4(uint32_t* r, uint32_t addr) {
    asm volatile("ldmatrix.sync.aligned.m8n8.x4.shared.b16 {%0,%1,%2,%3}, [%4];"
        : "=r"(r[0]), "=r"(r[1]), "=r"(r[2]), "=r"(r[3]) : "r"(addr));
}

// bf16 tile: 128 rows x 128B (64 bf16), 16B granules g=0..7, XOR swizzle
// (R3/R6-proven; conflict-free for ldmatrix rows and LDS.32 B-frags)
__device__ __forceinline__ uint32_t bswz(int n, int g) {
    return (uint32_t)(n * 128 + (((g ^ (n & 7)) & 7) << 4));
}

// ---------------------------------------------------------------------------
// 1) prep: blocks 0..127 -> wsT row n; blocks 128..159 zero Rpart  (R6-proven)
// ---------------------------------------------------------------------------
__global__ void prep_kernel(const float* __restrict__ wx, const float* __restrict__ wy,
                            const float* __restrict__ wsx, const float* __restrict__ wsy) {
    int blk = blockIdx.x, tid = threadIdx.x;
    if (blk < 128) {
        int n = blk;
        __shared__ float gx[64], gy[36], invz;
        if (tid < 64) {
            float rx = fmaxf(wsx[n], 0.0f);
            float inv2sx = 1.0f / (2.0f * (0.1f + rx * rx));
            float xv = ((float)tid - 32.0f + 0.5f) / 64.0f;
            float d = xv - wx[n];
            gx[tid] = expf(-d * d * inv2sx);
        } else if (tid < 100) {
            int yp = tid - 64;
            float ry = fmaxf(wsy[n], 0.0f);
            float inv2sy = 1.0f / (2.0f * (0.1f + ry * ry));
            float yv = ((float)yp - 18.0f + 0.5f) / 36.0f;
            float d = yv - wy[n];
            gy[yp] = expf(-d * d * inv2sy);
        }
        __syncthreads();
        if (tid == 0) {
            float sgx = 0.0f, sgy = 0.0f;
            for (int i = 0; i < 64; i++) sgx += gx[i];
            for (int i = 0; i < 36; i++) sgy += gy[i];
            invz = 1.0f / (0.1f + sgx * sgy);
        }
        __syncthreads();
        float iz = invz;
        for (int s = tid; s < S_; s += 256)
            g_wsT[(size_t)n * S_ + s] = __float2bfloat16(gy[s >> 6] * gx[s & 63] * iz);
    } else {
        int base = (blk - 128) * 2560;
        for (int q = tid; q < 2560; q += 256) g_Rpart[base + q] = 0.0f;
    }
}

// ---------------------------------------------------------------------------
// 2) GEMM: grid 148, 512 threads, 3-stage, one barrier per chunk.
//    A: LDG fp32 -> cvt bf16 -> STS (2-chunk reg lookahead); frags via ldmatrix.
//    B: cp.async bf16 (R12 path).
// ---------------------------------------------------------------------------
#define SM_A    0          // 3 x 16384 (bf16)
#define SM_B    49152      // 3 x 16384 (bf16)
#define SM_T1   98304
#define T1_STRIDE 132
#define SMEM_SZ (98304 + 128*T1_STRIDE*4)   // 165888

extern "C" __global__ void __launch_bounds__(512, 1)
gemm_kernel(const float* __restrict__ x, const float* __restrict__ wc) {
    extern __shared__ __align__(16) char smem[];
    const uint32_t sb = smem_u32(smem);
    const int tid  = threadIdx.x;
    const int wid  = tid >> 5;
    const int lane = tid & 31;
    const int wm   = wid & 3;       // m block: rows wm*32..+31
    const int wn   = wid >> 2;      // n block: cols wn*32..+31
    const int lrow = lane >> 2;
    const int lq   = lane & 3;
    const int lr   = tid >> 2;      // loader row 0..127
    const int lz   = tid & 3;       // loader k-quarter (16 floats)
    // ldmatrix lane addressing: rows (lane&15), k-granule half (lane>>4)
    const int lmr  = lane & 15;
    const int lmh  = lane >> 4;

    const int bi = blockIdx.x;
    const int s  = (bi < NLONG) ? 39 * bi : 39 * NLONG + 38 * (bi - NLONG);
    const int e  = s + ((bi < NLONG) ? 39 : 38);

    // ---- A LDG staging (2-chunk lookahead in registers) ----
    float4 fa[2][4];
    auto ldA = [&](int g, int buf) {
        int m = g / NCHUNK;
        int k = g - m * NCHUNK;
        int gr = m * 128 + lr;
        int f  = gr >> 6;
        int c  = gr & 63;
        int bb = f / T_;
        int tt = f - bb * T_;
        const float4* as = (const float4*)(x + ((size_t)((bb * C_ + c) * T_ + tt)) * S_
                                             + k * KC + lz * 16);
#pragma unroll
        for (int q = 0; q < 4; q++) fa[buf][q] = __ldg(as + q);
    };
    auto stsA = [&](int buf, int stage) {
        uint32_t v[8];
#pragma unroll
        for (int q = 0; q < 4; q++) {
            v[2*q]   = pack_bf16(fa[buf][q].x, fa[buf][q].y);
            v[2*q+1] = pack_bf16(fa[buf][q].z, fa[buf][q].w);
        }
        uint32_t ab = sb + SM_A + (uint32_t)stage * 16384u;
        uint32_t d0 = ab + bswz(lr, lz * 2);
        uint32_t d1 = ab + bswz(lr, lz * 2 + 1);
        asm volatile("st.shared.v4.b32 [%0], {%1,%2,%3,%4};"
            :: "r"(d0), "r"(v[0]), "r"(v[1]), "r"(v[2]), "r"(v[3]) : "memory");
        asm volatile("st.shared.v4.b32 [%0], {%1,%2,%3,%4};"
            :: "r"(d1), "r"(v[4]), "r"(v[5]), "r"(v[6]), "r"(v[7]) : "memory");
    };
    auto issueB = [&](int g, int stage) {
        int m = g / NCHUNK;
        int k = g - m * NCHUNK;
        uint32_t bb2 = sb + SM_B + (uint32_t)stage * 16384u;
        const __nv_bfloat16* bs = g_wsT + (size_t)lr * S_ + k * KC;
#pragma unroll
        for (int jj = 0; jj < 2; jj++) {
            int gB = lz * 2 + jj;
            cp16(bb2 + bswz(lr, gB), bs + gB * 8);
        }
    };

    float acc[2][4][4];
#pragma unroll
    for (int mt = 0; mt < 2; mt++)
#pragma unroll
        for (int j = 0; j < 4; j++)
#pragma unroll
            for (int q = 0; q < 4; q++) acc[mt][j][q] = 0.0f;

    ldA(s, 0);
    ldA(s + 1, 1);
    issueB(s, 0);     CP_COMMIT();
    issueB(s + 1, 1); CP_COMMIT();

    float* Tsm = (float*)(smem + SM_T1);
    int pb = 0;                      // stage of chunk g

    for (int g = s; g < e; g++) {
        stsA((g - s) & 1, pb);       // A chunk g: regs -> SMEM stage pb
        CP_WAIT1();                  // B chunk g complete
        __syncthreads();             // A STS + B visible to all
        if (g + 2 < e) ldA(g + 2, (g - s) & 1);

        const uint32_t Ab = sb + SM_A + (uint32_t)pb * 16384u;
        const uint32_t Bb = sb + SM_B + (uint32_t)pb * 16384u;
#pragma unroll
        for (int q = 0; q < 4; q++) {
            uint32_t afr[2][4];
#pragma unroll
            for (int mt = 0; mt < 2; mt++)
                ldmx4(afr[mt], Ab + bswz(wm * 32 + mt * 16 + lmr, q * 2 + lmh));
            uint32_t bfr[4][2];
#pragma unroll
            for (int j = 0; j < 4; j++) {
                int n = wn * 32 + j * 8 + lrow;
#pragma unroll
                for (int half = 0; half < 2; half++) {
                    asm volatile("ld.shared.b32 %0, [%1];"
                        : "=r"(bfr[j][half]) : "r"(Bb + bswz(n, q * 2 + half) + lq * 4));
                }
            }
#pragma unroll
            for (int mt = 0; mt < 2; mt++)
#pragma unroll
                for (int j = 0; j < 4; j++)
                    mma_bf16(acc[mt][j], afr[mt], bfr[j]);
        }

        // issue B chunk g+2 into stage consumed at g-1 (all readers passed
        // this iteration's barrier)
        if (g + 2 < e) {
            int pn = pb + 2; if (pn >= 3) pn -= 3;
            issueB(g + 2, pn);
        }
        CP_COMMIT();

        // ---- tile boundary or range end: flush partial R ----
        if ((g + 1 == e) || ((g + 1) % NCHUNK == 0)) {
            int m = g / NCHUNK;
            __syncthreads();
#pragma unroll
            for (int mt = 0; mt < 2; mt++) {
#pragma unroll
                for (int j = 0; j < 4; j++) {
                    int r0  = wm * 32 + mt * 16 + lrow;
                    int col = wn * 32 + j * 8 + lq * 2;
                    uint32_t a0 = sb + SM_T1 + (uint32_t)((r0 * T1_STRIDE + col) * 4);
                    uint32_t a1 = sb + SM_T1 + (uint32_t)(((r0 + 8) * T1_STRIDE + col) * 4);
                    asm volatile("st.shared.v2.f32 [%0], {%1,%2};"
                                 :: "r"(a0), "f"(acc[mt][j][0]), "f"(acc[mt][j][1]));
                    asm volatile("st.shared.v2.f32 [%0], {%1,%2};"
                                 :: "r"(a1), "f"(acc[mt][j][2]), "f"(acc[mt][j][3]));
                }
            }
            __syncthreads();
            if (tid < 256) {
                int fl = tid >> 7;
                int n  = tid & 127;
                float sum = 0.0f;
#pragma unroll 16
                for (int c2 = 0; c2 < 64; c2++)
                    sum += Tsm[(fl * 64 + c2) * T1_STRIDE + n] * __ldg(&wc[c2 * N_ + n]);
                int ord = (s > m * NCHUNK) ? 1 : 0;
                g_Rpart[m * 512 + ord * 256 + fl * 128 + n] = sum;
            }
#pragma unroll
            for (int mt = 0; mt < 2; mt++)
#pragma unroll
                for (int j = 0; j < 4; j++)
#pragma unroll
                    for (int q = 0; q < 4; q++) acc[mt][j][q] = 0.0f;
        }

        if (++pb >= 3) pb = 0;
    }
}

// ---------------------------------------------------------------------------
// 3) temporal conv: one warp per (b, n) row
// ---------------------------------------------------------------------------
__global__ void conv_kernel(const float* __restrict__ wt, const float* __restrict__ wb,
                            float* __restrict__ out) {
    __shared__ float rr[8][80];
    __shared__ float wts[8][10];
    int wid = threadIdx.x >> 5, lane = threadIdx.x & 31;
    int row = blockIdx.x * 8 + wid;        // row = b*N + n
    int b = row >> 7, n = row & 127;
    if (lane < 10) wts[wid][lane] = wt[lane * N_ + n];
#pragma unroll
    for (int t0 = lane; t0 < T_; t0 += 32) {
        int f = b * T_ + t0;
        int m = f >> 1, fl = f & 1;
        rr[wid][t0] = g_Rpart[m * 512 + fl * 128 + n]
                    + g_Rpart[m * 512 + 256 + fl * 128 + n];
    }
    __syncwarp();
    float bias = wb[n];
    for (int t0 = lane; t0 < TOUT_; t0 += 32) {
        float sum = bias;
#pragma unroll
        for (int k = 0; k < NT_; k++) sum += rr[wid][t0 + k] * wts[wid][k];
        out[(size_t)row * TOUT_ + t0] = sum;
    }
}

// ---------------------------------------------------------------------------
extern "C" void kernel_launch(void* const* d_in, const int* in_sizes, int n_in,
                              void* d_out, int out_size) {
    (void)in_sizes; (void)n_in; (void)out_size;
    const float* x   = (const float*)d_in[0];
    const float* wc  = (const float*)d_in[2];
    const float* wx  = (const float*)d_in[3];
    const float* wy  = (const float*)d_in[4];
    const float* wsx = (const float*)d_in[5];
    const float* wsy = (const float*)d_in[6];
    const float* wt  = (const float*)d_in[7];
    const float* wb  = (const float*)d_in[8];
    float* out = (float*)d_out;

    cudaFuncSetAttribute(gemm_kernel, cudaFuncAttributeMaxDynamicSharedMemorySize, SMEM_SZ);

    prep_kernel<<<160, 256>>>(wx, wy, wsx, wsy);
    gemm_kernel<<<GRID_G, 512, SMEM_SZ>>>(x, wc);
    conv_kernel<<<(B_ * N_) / 8, 256>>>(wt, wb, out);
}

// round 14
// speedup vs baseline: 1.3548x; 1.3548x over previous
#include <cuda_runtime.h>
#include <cuda_bf16.h>
#include <cstdint>

#define B_    4
#define C_    64
#define T_    80
#define S_    2304
#define N_    128
#define NT_   10
#define TOUT_ 71
#define F_    320
#define KC    64
#define NCHUNK 36                 // chunks per tile
#define NTILE  160                // M128 tiles
#define GRID_G 296                // 2 CTAs per SM
#define NLONG2 136                // CTAs with 20 chunks; remaining 160 have 19

// ---------------- device scratch -------------------------------------------
__device__ __align__(16) __nv_bfloat16 g_wsT[N_*S_];    // [n][s] bf16
__device__ float g_Rpart[NTILE*3*4*N_];                  // [tile][ord(3)][wm(4)][n]

// ---------------- helpers ---------------------------------------------------
__device__ __forceinline__ uint32_t smem_u32(const void* p) {
    uint32_t a;
    asm("{ .reg .u64 t; cvta.to.shared.u64 t, %1; cvt.u32.u64 %0, t; }" : "=r"(a) : "l"(p));
    return a;
}
__device__ __forceinline__ uint32_t pack_bf16(float lo, float hi) {
    uint32_t r;
    asm("cvt.rn.bf16x2.f32 %0, %1, %2;" : "=r"(r) : "f"(hi), "f"(lo));
    return r;
}
__device__ __forceinline__ void cp16(uint32_t dst, const void* src) {
    asm volatile("cp.async.cg.shared.global [%0], [%1], 16;" :: "r"(dst), "l"(src) : "memory");
}
#define CP_COMMIT() asm volatile("cp.async.commit_group;" ::: "memory")
#define CP_WAIT1()  asm volatile("cp.async.wait_group 1;" ::: "memory")

__device__ __forceinline__ void mma_bf16(float* d, const uint32_t* a, const uint32_t* b) {
    asm volatile("mma.sync.aligned.m16n8k16.row.col.f32.bf16.bf16.f32 "
        "{%0,%1,%2,%3}, {%4,%5,%6,%7}, {%8,%9}, {%0,%1,%2,%3};"
        : "+f"(d[0]), "+f"(d[1]), "+f"(d[2]), "+f"(d[3])
        : "r"(a[0]), "r"(a[1]), "r"(a[2]), "r"(a[3]), "r"(b[0]), "r"(b[1]));
}

// A: fp32 tile 128 rows x 256B, 32B granules g=0..7, XOR swizzle (R3/R6/R12-proven)
__device__ __forceinline__ uint32_t aswz(int r, int g) {
    return (uint32_t)(r * 256 + (((g ^ (r & 7)) & 7) << 5));
}
// B: bf16 tile 128 rows x 128B, 16B granules (R3/R6/R12-proven)
__device__ __forceinline__ uint32_t bswz(int n, int g) {
    return (uint32_t)(n * 128 + (((g ^ (n & 7)) & 7) << 4));
}

// ---------------------------------------------------------------------------
// 1) prep: blocks 0..127 -> wsT row n; blocks 128..159 zero Rpart
// ---------------------------------------------------------------------------
__global__ void prep_kernel(const float* __restrict__ wx, const float* __restrict__ wy,
                            const float* __restrict__ wsx, const float* __restrict__ wsy) {
    int blk = blockIdx.x, tid = threadIdx.x;
    if (blk < 128) {
        int n = blk;
        __shared__ float gx[64], gy[36], invz;
        if (tid < 64) {
            float rx = fmaxf(wsx[n], 0.0f);
            float inv2sx = 1.0f / (2.0f * (0.1f + rx * rx));
            float xv = ((float)tid - 32.0f + 0.5f) / 64.0f;
            float d = xv - wx[n];
            gx[tid] = expf(-d * d * inv2sx);
        } else if (tid < 100) {
            int yp = tid - 64;
            float ry = fmaxf(wsy[n], 0.0f);
            float inv2sy = 1.0f / (2.0f * (0.1f + ry * ry));
            float yv = ((float)yp - 18.0f + 0.5f) / 36.0f;
            float d = yv - wy[n];
            gy[yp] = expf(-d * d * inv2sy);
        }
        __syncthreads();
        if (tid == 0) {
            float sgx = 0.0f, sgy = 0.0f;
            for (int i = 0; i < 64; i++) sgx += gx[i];
            for (int i = 0; i < 36; i++) sgy += gy[i];
            invz = 1.0f / (0.1f + sgx * sgy);
        }
        __syncthreads();
        float iz = invz;
        for (int s = tid; s < S_; s += 256)
            g_wsT[(size_t)n * S_ + s] = __float2bfloat16(gy[s >> 6] * gx[s & 63] * iz);
    } else {
        int base = (blk - 128) * 7680;           // 32 blocks x 7680 = 245760
        for (int q = tid; q < 7680; q += 256) g_Rpart[base + q] = 0.0f;
    }
}

// ---------------------------------------------------------------------------
// 2) GEMM: grid 296 (2 CTAs/SM), 512 threads, 2-stage cp.async,
//    R12 datapath, register-only epilogue (no T1 SMEM).
// ---------------------------------------------------------------------------
#define SM_A    0          // 2 x 32768 (fp32)
#define SM_B    65536      // 2 x 16384 (bf16)
#define SMEM_SZ 98304

extern "C" __global__ void __launch_bounds__(512, 2)
gemm_kernel(const float* __restrict__ x, const float* __restrict__ wc) {
    extern __shared__ __align__(16) char smem[];
    const uint32_t sb = smem_u32(smem);
    const int tid  = threadIdx.x;
    const int wid  = tid >> 5;
    const int lane = tid & 31;
    const int wm   = wid & 3;       // m block: rows wm*32..+31
    const int wn   = wid >> 2;      // n block: cols wn*32..+31
    const int lrow = lane >> 2;
    const int lq   = lane & 3;
    const int lr   = tid >> 2;      // loader row 0..127
    const int lz   = tid & 3;       // loader quarter

    const int bi = blockIdx.x;
    const int s   = (bi < NLONG2) ? 20 * bi : 2720 + 19 * (bi - NLONG2);
    const int len = (bi < NLONG2) ? 20 : 19;
    const int e   = s + len;
    const int sprev = (bi == 0) ? 0 : s - ((bi - 1 < NLONG2) ? 20 : 19);

    auto issue = [&](int g, int p) {
        int m = g / NCHUNK;
        int k = g - m * NCHUNK;
        int gr = m * 128 + lr;
        int f  = gr >> 6;
        int c  = gr & 63;
        int bb = f / T_;
        int tt = f - bb * T_;
        const float* xrow = x + ((size_t)((bb * C_ + c) * T_ + tt)) * S_ + k * KC;
        uint32_t ab  = sb + SM_A + (uint32_t)p * 32768u;
        uint32_t bb2 = sb + SM_B + (uint32_t)p * 16384u;
#pragma unroll
        for (int jj = 0; jj < 2; jj++) {
            int gA = lz * 2 + jj;                 // 32B granule
            uint32_t d = ab + aswz(lr, gA);
            cp16(d,      xrow + gA * 8);
            cp16(d + 16, xrow + gA * 8 + 4);
        }
        const __nv_bfloat16* bs = g_wsT + (size_t)lr * S_ + k * KC;
#pragma unroll
        for (int jj = 0; jj < 2; jj++) {
            int gB = lz * 2 + jj;                 // 16B granule
            cp16(bb2 + bswz(lr, gB), bs + gB * 8);
        }
    };

    float acc[2][4][4];
#pragma unroll
    for (int mt = 0; mt < 2; mt++)
#pragma unroll
        for (int j = 0; j < 4; j++)
#pragma unroll
            for (int q = 0; q < 4; q++) acc[mt][j][q] = 0.0f;

    issue(s, 0);     CP_COMMIT();
    issue(s + 1, 1); CP_COMMIT();

    for (int g = s; g < e; g++) {
        const int p = (g - s) & 1;
        CP_WAIT1();
        __syncthreads();                 // chunk g data ready

        const uint32_t Ab = sb + SM_A + (uint32_t)p * 32768u;
        const uint32_t Bb = sb + SM_B + (uint32_t)p * 16384u;
#pragma unroll
        for (int q = 0; q < 4; q++) {
            uint32_t bfr[4][2];
#pragma unroll
            for (int j = 0; j < 4; j++) {
                int n = wn * 32 + j * 8 + lrow;
#pragma unroll
                for (int half = 0; half < 2; half++) {
                    asm volatile("ld.shared.b32 %0, [%1];"
                        : "=r"(bfr[j][half]) : "r"(Bb + bswz(n, q * 2 + half) + lq * 4));
                }
            }
#pragma unroll
            for (int mt = 0; mt < 2; mt++) {
                uint32_t afr[4];
#pragma unroll
                for (int half = 0; half < 2; half++) {
#pragma unroll
                    for (int dr = 0; dr < 2; dr++) {
                        float2 v;
                        uint32_t ad = Ab + aswz(wm * 32 + mt * 16 + lrow + dr * 8,
                                                q * 2 + half) + lq * 8;
                        asm volatile("ld.shared.v2.f32 {%0,%1}, [%2];"
                                     : "=f"(v.x), "=f"(v.y) : "r"(ad));
                        afr[half * 2 + dr] = pack_bf16(v.x, v.y);
                    }
                }
#pragma unroll
                for (int j = 0; j < 4; j++)
                    mma_bf16(acc[mt][j], afr, bfr[j]);
            }
        }
        __syncthreads();                 // stage p fully consumed
        if (g + 2 < e) issue(g + 2, p);
        CP_COMMIT();

        // ---- tile boundary or range end: register-only flush ----
        if ((g + 1 == e) || ((g + 1) % NCHUNK == 0)) {
            int m = g / NCHUNK;
            int ord = (s <= m * NCHUNK) ? 0 : ((sprev > m * NCHUNK) ? 2 : 1);
            float* slot = g_Rpart + (size_t)((m * 3 + ord) * 4 + wm) * N_;
#pragma unroll
            for (int j = 0; j < 4; j++) {
                int n0 = wn * 32 + j * 8 + lq * 2;
                float v0 = 0.0f, v1 = 0.0f;
#pragma unroll
                for (int mt = 0; mt < 2; mt++) {
                    int c0 = (wm & 1) * 32 + mt * 16 + lrow;
                    int c1 = c0 + 8;
                    float w00 = __ldg(&wc[c0 * N_ + n0]);
                    float w01 = __ldg(&wc[c0 * N_ + n0 + 1]);
                    float w10 = __ldg(&wc[c1 * N_ + n0]);
                    float w11 = __ldg(&wc[c1 * N_ + n0 + 1]);
                    v0 += acc[mt][j][0] * w00 + acc[mt][j][2] * w10;
                    v1 += acc[mt][j][1] * w01 + acc[mt][j][3] * w11;
                }
#pragma unroll
                for (int off = 4; off <= 16; off <<= 1) {
                    v0 += __shfl_xor_sync(0xFFFFFFFFu, v0, off);
                    v1 += __shfl_xor_sync(0xFFFFFFFFu, v1, off);
                }
                if (lane < 4) {
                    slot[n0]     = v0;
                    slot[n0 + 1] = v1;
                }
            }
#pragma unroll
            for (int mt = 0; mt < 2; mt++)
#pragma unroll
                for (int j = 0; j < 4; j++)
#pragma unroll
                    for (int q = 0; q < 4; q++) acc[mt][j][q] = 0.0f;
        }
    }
}

// ---------------------------------------------------------------------------
// 3) temporal conv: one warp per (b, n) row; R[f] = sum of 6 slots (3 ord x 2 par)
// ---------------------------------------------------------------------------
__global__ void conv_kernel(const float* __restrict__ wt, const float* __restrict__ wb,
                            float* __restrict__ out) {
    __shared__ float rr[8][80];
    __shared__ float wts[8][10];
    int wid = threadIdx.x >> 5, lane = threadIdx.x & 31;
    int row = blockIdx.x * 8 + wid;        // row = b*N + n
    int b = row >> 7, n = row & 127;
    if (lane < 10) wts[wid][lane] = wt[lane * N_ + n];
#pragma unroll
    for (int t0 = lane; t0 < T_; t0 += 32) {
        int f = b * T_ + t0;
        int m = f >> 1, fl = f & 1;
        float sum = 0.0f;
#pragma unroll
        for (int ord = 0; ord < 3; ord++) {
#pragma unroll
            for (int par = 0; par < 2; par++)
                sum += g_Rpart[(size_t)((m * 3 + ord) * 4 + fl * 2 + par) * N_ + n];
        }
        rr[wid][t0] = sum;
    }
    __syncwarp();
    float bias = wb[n];
    for (int t0 = lane; t0 < TOUT_; t0 += 32) {
        float sum = bias;
#pragma unroll
        for (int k = 0; k < NT_; k++) sum += rr[wid][t0 + k] * wts[wid][k];
        out[(size_t)row * TOUT_ + t0] = sum;
    }
}

// ---------------------------------------------------------------------------
extern "C" void kernel_launch(void* const* d_in, const int* in_sizes, int n_in,
                              void* d_out, int out_size) {
    (void)in_sizes; (void)n_in; (void)out_size;
    const float* x   = (const float*)d_in[0];
    const float* wc  = (const float*)d_in[2];
    const float* wx  = (const float*)d_in[3];
    const float* wy  = (const float*)d_in[4];
    const float* wsx = (const float*)d_in[5];
    const float* wsy = (const float*)d_in[6];
    const float* wt  = (const float*)d_in[7];
    const float* wb  = (const float*)d_in[8];
    float* out = (float*)d_out;

    cudaFuncSetAttribute(gemm_kernel, cudaFuncAttributeMaxDynamicSharedMemorySize, SMEM_SZ);

    prep_kernel<<<160, 256>>>(wx, wy, wsx, wsy);
    gemm_kernel<<<GRID_G, 512, SMEM_SZ>>>(x, wc);
    conv_kernel<<<(B_ * N_) / 8, 256>>>(wt, wb, out);
}

// round 15
// speedup vs baseline: 1.4615x; 1.0787x over previous
#include <cuda_runtime.h>
#include <cuda_bf16.h>
#include <cstdint>

#define B_    4
#define C_    64
#define T_    80
#define S_    2304
#define N_    128
#define NT_   10
#define TOUT_ 71
#define F_    320
#define KC    64
#define NCHUNK 36                 // chunks per tile
#define NTILE  160                // M128 tiles
#define GRID_G 152                // GB300 has 152 SMs
#define NLONG  136                // CTAs with 38 chunks; remaining 16 have 37

// ---------------- device scratch -------------------------------------------
__device__ __align__(16) __nv_bfloat16 g_wsT[N_*S_];    // [n][s] bf16
__device__ float g_R2[2*B_*N_*T_];                       // [ord][b][n][t]

// ---------------- helpers ---------------------------------------------------
__device__ __forceinline__ uint32_t smem_u32(const void* p) {
    uint32_t a;
    asm("{ .reg .u64 t; cvta.to.shared.u64 t, %1; cvt.u32.u64 %0, t; }" : "=r"(a) : "l"(p));
    return a;
}
__device__ __forceinline__ uint32_t pack_bf16(float lo, float hi) {
    uint32_t r;
    asm("cvt.rn.bf16x2.f32 %0, %1, %2;" : "=r"(r) : "f"(hi), "f"(lo));
    return r;
}
__device__ __forceinline__ void cp16(uint32_t dst, const void* src) {
    asm volatile("cp.async.cg.shared.global [%0], [%1], 16;" :: "r"(dst), "l"(src) : "memory");
}
#define CP_COMMIT() asm volatile("cp.async.commit_group;" ::: "memory")
#define CP_WAIT1()  asm volatile("cp.async.wait_group 1;" ::: "memory")

__device__ __forceinline__ void mma_bf16(float* d, const uint32_t* a, const uint32_t* b) {
    asm volatile("mma.sync.aligned.m16n8k16.row.col.f32.bf16.bf16.f32 "
        "{%0,%1,%2,%3}, {%4,%5,%6,%7}, {%8,%9}, {%0,%1,%2,%3};"
        : "+f"(d[0]), "+f"(d[1]), "+f"(d[2]), "+f"(d[3])
        : "r"(a[0]), "r"(a[1]), "r"(a[2]), "r"(a[3]), "r"(b[0]), "r"(b[1]));
}

// A: fp32 tile 128 rows x 256B, 32B granules g=0..7, XOR swizzle (R3/R6/R12-proven)
__device__ __forceinline__ uint32_t aswz(int r, int g) {
    return (uint32_t)(r * 256 + (((g ^ (r & 7)) & 7) << 5));
}
// B: bf16 tile 128 rows x 128B, 16B granules (R3/R6/R12-proven)
__device__ __forceinline__ uint32_t bswz(int n, int g) {
    return (uint32_t)(n * 128 + (((g ^ (n & 7)) & 7) << 4));
}

// ---------------------------------------------------------------------------
// 1) prep: blocks 0..127 -> wsT row n (parallel reductions);
//    blocks 128..191 zero g_R2 (81920 floats / 64 blocks)
// ---------------------------------------------------------------------------
__global__ void prep_kernel(const float* __restrict__ wx, const float* __restrict__ wy,
                            const float* __restrict__ wsx, const float* __restrict__ wsy) {
    int blk = blockIdx.x, tid = threadIdx.x;
    if (blk < 128) {
        int n = blk;
        int lane = tid & 31;
        __shared__ float gx[64], gy[36], red[2];
        if (tid < 64) {
            float rx = fmaxf(wsx[n], 0.0f);
            float inv2sx = 1.0f / (2.0f * (0.1f + rx * rx));
            float xv = ((float)tid - 32.0f + 0.5f) / 64.0f;
            float d = xv - wx[n];
            gx[tid] = expf(-d * d * inv2sx);
        } else if (tid < 100) {
            int yp = tid - 64;
            float ry = fmaxf(wsy[n], 0.0f);
            float inv2sy = 1.0f / (2.0f * (0.1f + ry * ry));
            float yv = ((float)yp - 18.0f + 0.5f) / 36.0f;
            float d = yv - wy[n];
            gy[yp] = expf(-d * d * inv2sy);
        }
        __syncthreads();
        int wz = tid >> 5;
        if (wz == 0) {
            float v = gx[lane] + gx[lane + 32];
#pragma unroll
            for (int off = 16; off; off >>= 1) v += __shfl_xor_sync(0xFFFFFFFFu, v, off);
            if (lane == 0) red[0] = v;
        } else if (wz == 1) {
            float v = gy[lane];
            if (lane < 4) v += gy[32 + lane];
#pragma unroll
            for (int off = 16; off; off >>= 1) v += __shfl_xor_sync(0xFFFFFFFFu, v, off);
            if (lane == 0) red[1] = v;
        }
        __syncthreads();
        float iz = 1.0f / (0.1f + red[0] * red[1]);
        for (int s = tid; s < S_; s += 256)
            g_wsT[(size_t)n * S_ + s] = __float2bfloat16(gy[s >> 6] * gx[s & 63] * iz);
    } else {
        int base = (blk - 128) * 1280;           // 64 blocks x 1280 = 81920
        for (int q = tid; q < 1280; q += 256) g_R2[base + q] = 0.0f;
    }
}

// ---------------------------------------------------------------------------
// 2) GEMM: grid 152, 512 threads, 3-stage cp.async, ONE barrier per chunk.
//    (R12 datapath, byte-identical inner loop.)
// ---------------------------------------------------------------------------
#define SM_A    0          // 3 x 32768
#define SM_B    98304      // 3 x 16384
#define SM_T1   147456
#define T1_STRIDE 132
#define SMEM_SZ (147456 + 128*T1_STRIDE*4)   // 215040

extern "C" __global__ void __launch_bounds__(512, 1)
gemm_kernel(const float* __restrict__ x, const float* __restrict__ wc) {
    extern __shared__ __align__(16) char smem[];
    const uint32_t sb = smem_u32(smem);
    const int tid  = threadIdx.x;
    const int wid  = tid >> 5;
    const int lane = tid & 31;
    const int wm   = wid & 3;       // m block: rows wm*32..+31
    const int wn   = wid >> 2;      // n block: cols wn*32..+31
    const int lrow = lane >> 2;
    const int lq   = lane & 3;
    const int lr   = tid >> 2;      // loader row 0..127
    const int lz   = tid & 3;       // loader quarter

    const int bi = blockIdx.x;
    const int s  = (bi < NLONG) ? 38 * bi : 38 * NLONG + 37 * (bi - NLONG);
    const int e  = s + ((bi < NLONG) ? 38 : 37);

    auto issue = [&](int g, int p) {
        int m = g / NCHUNK;
        int k = g - m * NCHUNK;
        int gr = m * 128 + lr;
        int f  = gr >> 6;
        int c  = gr & 63;
        int bb = f / T_;
        int tt = f - bb * T_;
        const float* xrow = x + ((size_t)((bb * C_ + c) * T_ + tt)) * S_ + k * KC;
        uint32_t ab = sb + SM_A + (uint32_t)p * 32768u;
        uint32_t bb2 = sb + SM_B + (uint32_t)p * 16384u;
#pragma unroll
        for (int jj = 0; jj < 2; jj++) {
            int gA = lz * 2 + jj;                 // 32B granule
            uint32_t d = ab + aswz(lr, gA);
            cp16(d,      xrow + gA * 8);
            cp16(d + 16, xrow + gA * 8 + 4);
        }
        const __nv_bfloat16* bs = g_wsT + (size_t)lr * S_ + k * KC;
#pragma unroll
        for (int jj = 0; jj < 2; jj++) {
            int gB = lz * 2 + jj;                 // 16B granule
            cp16(bb2 + bswz(lr, gB), bs + gB * 8);
        }
    };

    float acc[2][4][4];
#pragma unroll
    for (int mt = 0; mt < 2; mt++)
#pragma unroll
        for (int j = 0; j < 4; j++)
#pragma unroll
            for (int q = 0; q < 4; q++) acc[mt][j][q] = 0.0f;

    issue(s, 0);     CP_COMMIT();
    issue(s + 1, 1); CP_COMMIT();

    float* Tsm = (float*)(smem + SM_T1);
    int pb = 0;                      // stage of chunk g

    for (int g = s; g < e; g++) {
        CP_WAIT1();
        __syncthreads();

        const uint32_t Ab = sb + SM_A + (uint32_t)pb * 32768u;
        const uint32_t Bb = sb + SM_B + (uint32_t)pb * 16384u;
#pragma unroll
        for (int q = 0; q < 4; q++) {
            uint32_t afr[2][4];
#pragma unroll
            for (int mt = 0; mt < 2; mt++) {
#pragma unroll
                for (int half = 0; half < 2; half++) {
#pragma unroll
                    for (int dr = 0; dr < 2; dr++) {
                        float2 v;
                        uint32_t ad = Ab + aswz(wm * 32 + mt * 16 + lrow + dr * 8,
                                                q * 2 + half) + lq * 8;
                        asm volatile("ld.shared.v2.f32 {%0,%1}, [%2];"
                                     : "=f"(v.x), "=f"(v.y) : "r"(ad));
                        afr[mt][half * 2 + dr] = pack_bf16(v.x, v.y);
                    }
                }
            }
            uint32_t bfr[4][2];
#pragma unroll
            for (int j = 0; j < 4; j++) {
                int n = wn * 32 + j * 8 + lrow;
#pragma unroll
                for (int half = 0; half < 2; half++) {
                    asm volatile("ld.shared.b32 %0, [%1];"
                        : "=r"(bfr[j][half]) : "r"(Bb + bswz(n, q * 2 + half) + lq * 4));
                }
            }
#pragma unroll
            for (int mt = 0; mt < 2; mt++)
#pragma unroll
                for (int j = 0; j < 4; j++)
                    mma_bf16(acc[mt][j], afr[mt], bfr[j]);
        }

        // issue chunk g+2 into stage (pb+2)%3 == buffer consumed at g-1 (safe:
        // all its readers passed this iteration's __syncthreads).
        if (g + 2 < e) {
            int pn = pb + 2; if (pn >= 3) pn -= 3;
            issue(g + 2, pn);
        }
        CP_COMMIT();

        // ---- tile boundary or range end: flush partial R ----
        if ((g + 1 == e) || ((g + 1) % NCHUNK == 0)) {
            int m = g / NCHUNK;
            __syncthreads();
#pragma unroll
            for (int mt = 0; mt < 2; mt++) {
#pragma unroll
                for (int j = 0; j < 4; j++) {
                    int r0  = wm * 32 + mt * 16 + lrow;
                    int col = wn * 32 + j * 8 + lq * 2;
                    uint32_t a0 = sb + SM_T1 + (uint32_t)((r0 * T1_STRIDE + col) * 4);
                    uint32_t a1 = sb + SM_T1 + (uint32_t)(((r0 + 8) * T1_STRIDE + col) * 4);
                    asm volatile("st.shared.v2.f32 [%0], {%1,%2};"
                                 :: "r"(a0), "f"(acc[mt][j][0]), "f"(acc[mt][j][1]));
                    asm volatile("st.shared.v2.f32 [%0], {%1,%2};"
                                 :: "r"(a1), "f"(acc[mt][j][2]), "f"(acc[mt][j][3]));
                }
            }
            __syncthreads();
            if (tid < 256) {
                int fl = tid >> 7;
                int n  = tid & 127;
                float sum = 0.0f;
#pragma unroll 16
                for (int c2 = 0; c2 < 64; c2++)
                    sum += Tsm[(fl * 64 + c2) * T1_STRIDE + n] * __ldg(&wc[c2 * N_ + n]);
                int ord = (s > m * NCHUNK) ? 1 : 0;
                int f2 = m * 2 + fl;
                int b2 = f2 / T_;
                int t2 = f2 - b2 * T_;
                g_R2[(size_t)(ord * 512 + b2 * 128 + n) * T_ + t2] = sum;
            }
#pragma unroll
            for (int mt = 0; mt < 2; mt++)
#pragma unroll
                for (int j = 0; j < 4; j++)
#pragma unroll
                    for (int q = 0; q < 4; q++) acc[mt][j][q] = 0.0f;
        }

        if (++pb >= 3) pb = 0;
    }
}

// ---------------------------------------------------------------------------
// 3) temporal conv: one warp per (b, n) row; coalesced t-contiguous reads
// ---------------------------------------------------------------------------
__global__ void conv_kernel(const float* __restrict__ wt, const float* __restrict__ wb,
                            float* __restrict__ out) {
    __shared__ float rr[8][80];
    __shared__ float wts[8][10];
    int wid = threadIdx.x >> 5, lane = threadIdx.x & 31;
    int row = blockIdx.x * 8 + wid;        // row = b*N + n
    int n = row & 127;
    if (lane < 10) wts[wid][lane] = wt[lane * N_ + n];
    const float* r0 = g_R2 + (size_t)row * T_;
    const float* r1 = g_R2 + (size_t)(512 + row) * T_;
    rr[wid][lane]      = r0[lane]      + r1[lane];
    rr[wid][lane + 32] = r0[lane + 32] + r1[lane + 32];
    if (lane < 16) rr[wid][lane + 64] = r0[lane + 64] + r1[lane + 64];
    __syncwarp();
    float bias = wb[n];
    for (int t0 = lane; t0 < TOUT_; t0 += 32) {
        float sum = bias;
#pragma unroll
        for (int k = 0; k < NT_; k++) sum += rr[wid][t0 + k] * wts[wid][k];
        out[(size_t)row * TOUT_ + t0] = sum;
    }
}

// ---------------------------------------------------------------------------
extern "C" void kernel_launch(void* const* d_in, const int* in_sizes, int n_in,
                              void* d_out, int out_size) {
    (void)in_sizes; (void)n_in; (void)out_size;
    const float* x   = (const float*)d_in[0];
    const float* wc  = (const float*)d_in[2];
    const float* wx  = (const float*)d_in[3];
    const float* wy  = (const float*)d_in[4];
    const float* wsx = (const float*)d_in[5];
    const float* wsy = (const float*)d_in[6];
    const float* wt  = (const float*)d_in[7];
    const float* wb  = (const float*)d_in[8];
    float* out = (float*)d_out;

    cudaFuncSetAttribute(gemm_kernel, cudaFuncAttributeMaxDynamicSharedMemorySize, SMEM_SZ);

    prep_kernel<<<192, 256>>>(wx, wy, wsx, wsy);
    gemm_kernel<<<GRID_G, 512, SMEM_SZ>>>(x, wc);
    conv_kernel<<<(B_ * N_) / 8, 256>>>(wt, wb, out);
}

// round 16
// speedup vs baseline: 1.4981x; 1.0250x over previous
#include <cuda_runtime.h>
#include <cuda_bf16.h>
#include <cstdint>

#define B_    4
#define C_    64
#define T_    80
#define S_    2304
#define N_    128
#define NT_   10
#define TOUT_ 71
#define F_    320
#define KC    64
#define NCHUNK 36                 // chunks per tile
#define NTILE  160                // M128 tiles
#define GRID_G 152                // GB300 has 152 SMs
#define NLONG  136                // CTAs with 38 chunks; remaining 16 have 37

// ---------------- device scratch -------------------------------------------
__device__ float g_R2[2*B_*N_*T_];                       // [ord][b][n][t]

// ---------------- helpers ---------------------------------------------------
__device__ __forceinline__ uint32_t smem_u32(const void* p) {
    uint32_t a;
    asm("{ .reg .u64 t; cvta.to.shared.u64 t, %1; cvt.u32.u64 %0, t; }" : "=r"(a) : "l"(p));
    return a;
}
__device__ __forceinline__ uint32_t pack_bf16(float lo, float hi) {
    uint32_t r;
    asm("cvt.rn.bf16x2.f32 %0, %1, %2;" : "=r"(r) : "f"(hi), "f"(lo));
    return r;
}
__device__ __forceinline__ void cp16(uint32_t dst, const void* src) {
    asm volatile("cp.async.cg.shared.global [%0], [%1], 16;" :: "r"(dst), "l"(src) : "memory");
}
#define CP_COMMIT() asm volatile("cp.async.commit_group;" ::: "memory")
#define CP_WAIT1()  asm volatile("cp.async.wait_group 1;" ::: "memory")

__device__ __forceinline__ void mma_bf16(float* d, const uint32_t* a, const uint32_t* b) {
    asm volatile("mma.sync.aligned.m16n8k16.row.col.f32.bf16.bf16.f32 "
        "{%0,%1,%2,%3}, {%4,%5,%6,%7}, {%8,%9}, {%0,%1,%2,%3};"
        : "+f"(d[0]), "+f"(d[1]), "+f"(d[2]), "+f"(d[3])
        : "r"(a[0]), "r"(a[1]), "r"(a[2]), "r"(a[3]), "r"(b[0]), "r"(b[1]));
}

// A: fp32 tile 128 rows x 256B, 32B granules g=0..7, XOR swizzle (proven)
__device__ __forceinline__ uint32_t aswz(int r, int g) {
    return (uint32_t)(r * 256 + (((g ^ (r & 7)) & 7) << 5));
}
// B: bf16 tile 128 rows x 128B, 16B granules (proven)
__device__ __forceinline__ uint32_t bswz(int n, int g) {
    return (uint32_t)(n * 128 + (((g ^ (n & 7)) & 7) << 4));
}

// ---------------------------------------------------------------------------
// GEMM: grid 152, 512 threads, 3-stage cp.async A, rank-1 synthesized B.
// ---------------------------------------------------------------------------
#define SM_A    0          // 3 x 32768 (fp32)
#define SM_B    98304      // 2 x 16384 (bf16)
#define SM_GYZ  131072     // 36 x 128 fp32 = 18432
#define SM_T1   149504
#define T1_STRIDE 132
#define SMEM_SZ (149504 + 128*T1_STRIDE*4)   // 217088

extern "C" __global__ void __launch_bounds__(512, 1)
gemm_kernel(const float* __restrict__ x, const float* __restrict__ wc,
            const float* __restrict__ wx, const float* __restrict__ wy,
            const float* __restrict__ wsx, const float* __restrict__ wsy) {
    extern __shared__ __align__(16) char smem[];
    const uint32_t sb = smem_u32(smem);
    const int tid  = threadIdx.x;
    const int wid  = tid >> 5;
    const int lane = tid & 31;
    const int wm   = wid & 3;       // m block: rows wm*32..+31
    const int wn   = wid >> 2;      // n block: cols wn*32..+31
    const int lrow = lane >> 2;
    const int lq   = lane & 3;
    const int lr   = tid >> 2;      // loader/synth row 0..127
    const int lz   = tid & 3;       // loader/synth quarter

    const int bi = blockIdx.x;
    const int s  = (bi < NLONG) ? 38 * bi : 38 * NLONG + 37 * (bi - NLONG);
    const int e  = s + ((bi < NLONG) ? 38 : 37);

    float* gyzs = (float*)(smem + SM_GYZ);   // [k][n]

    // ---- startup: gx in registers (x = lz*16+i, n = lr), gyz table ----
    float gxr[16];
    {
        float rx = fmaxf(wsx[lr], 0.0f);
        float i2x = 1.0f / (2.0f * (0.1f + rx * rx));
        float cx = wx[lr];
        float sgx = 0.0f;
#pragma unroll
        for (int i = 0; i < 16; i++) {
            float xv = ((float)(lz * 16 + i) - 32.0f + 0.5f) / 64.0f;
            float d = xv - cx;
            gxr[i] = expf(-d * d * i2x);
            sgx += gxr[i];
        }
        sgx += __shfl_xor_sync(0xFFFFFFFFu, sgx, 1);
        sgx += __shfl_xor_sync(0xFFFFFFFFu, sgx, 2);

        float ry = fmaxf(wsy[lr], 0.0f);
        float i2y = 1.0f / (2.0f * (0.1f + ry * ry));
        float cy = wy[lr];
        float gyv[9];
        float sgy = 0.0f;
#pragma unroll
        for (int i = 0; i < 9; i++) {
            float yv = ((float)(lz * 9 + i) - 18.0f + 0.5f) / 36.0f;
            float d = yv - cy;
            gyv[i] = expf(-d * d * i2y);
            sgy += gyv[i];
        }
        sgy += __shfl_xor_sync(0xFFFFFFFFu, sgy, 1);
        sgy += __shfl_xor_sync(0xFFFFFFFFu, sgy, 2);

        float iz = 1.0f / (0.1f + sgx * sgy);
#pragma unroll
        for (int i = 0; i < 9; i++)
            gyzs[(lz * 9 + i) * N_ + lr] = gyv[i] * iz;
    }
    __syncthreads();

    auto issueA = [&](int g, int p) {
        int m = g / NCHUNK;
        int k = g - m * NCHUNK;
        int gr = m * 128 + lr;
        int f  = gr >> 6;
        int c  = gr & 63;
        int bb = f / T_;
        int tt = f - bb * T_;
        const float* xrow = x + ((size_t)((bb * C_ + c) * T_ + tt)) * S_ + k * KC;
        uint32_t ab = sb + SM_A + (uint32_t)p * 32768u;
#pragma unroll
        for (int jj = 0; jj < 2; jj++) {
            int gA = lz * 2 + jj;                 // 32B granule
            uint32_t d = ab + aswz(lr, gA);
            cp16(d,      xrow + gA * 8);
            cp16(d + 16, xrow + gA * 8 + 4);
        }
    };

    // rank-1 B synthesis: B[n][j] = gyz[k][n] * gx[j][n]
    auto synthB = [&](int g, int stage) {
        int m = g / NCHUNK;
        int k = g - m * NCHUNK;
        float sc = gyzs[k * N_ + lr];
        uint32_t v[8];
#pragma unroll
        for (int q = 0; q < 8; q++)
            v[q] = pack_bf16(gxr[2 * q] * sc, gxr[2 * q + 1] * sc);
        uint32_t bb2 = sb + SM_B + (uint32_t)stage * 16384u;
        uint32_t d0 = bb2 + bswz(lr, lz * 2);
        uint32_t d1 = bb2 + bswz(lr, lz * 2 + 1);
        asm volatile("st.shared.v4.b32 [%0], {%1,%2,%3,%4};"
            :: "r"(d0), "r"(v[0]), "r"(v[1]), "r"(v[2]), "r"(v[3]) : "memory");
        asm volatile("st.shared.v4.b32 [%0], {%1,%2,%3,%4};"
            :: "r"(d1), "r"(v[4]), "r"(v[5]), "r"(v[6]), "r"(v[7]) : "memory");
    };

    float acc[2][4][4];
#pragma unroll
    for (int mt = 0; mt < 2; mt++)
#pragma unroll
        for (int j = 0; j < 4; j++)
#pragma unroll
            for (int q = 0; q < 4; q++) acc[mt][j][q] = 0.0f;

    issueA(s, 0);     CP_COMMIT();
    issueA(s + 1, 1); CP_COMMIT();

    float* Tsm = (float*)(smem + SM_T1);
    int pb = 0;                      // A stage of chunk g

    for (int g = s; g < e; g++) {
        synthB(g, g & 1);            // write B(g) before the barrier
        CP_WAIT1();                  // A(g) complete
        __syncthreads();

        const uint32_t Ab = sb + SM_A + (uint32_t)pb * 32768u;
        const uint32_t Bb = sb + SM_B + (uint32_t)(g & 1) * 16384u;
#pragma unroll
        for (int q = 0; q < 4; q++) {
            uint32_t afr[2][4];
#pragma unroll
            for (int mt = 0; mt < 2; mt++) {
#pragma unroll
                for (int half = 0; half < 2; half++) {
#pragma unroll
                    for (int dr = 0; dr < 2; dr++) {
                        float2 v;
                        uint32_t ad = Ab + aswz(wm * 32 + mt * 16 + lrow + dr * 8,
                                                q * 2 + half) + lq * 8;
                        asm volatile("ld.shared.v2.f32 {%0,%1}, [%2];"
                                     : "=f"(v.x), "=f"(v.y) : "r"(ad));
                        afr[mt][half * 2 + dr] = pack_bf16(v.x, v.y);
                    }
                }
            }
            uint32_t bfr[4][2];
#pragma unroll
            for (int j = 0; j < 4; j++) {
                int n = wn * 32 + j * 8 + lrow;
#pragma unroll
                for (int half = 0; half < 2; half++) {
                    asm volatile("ld.shared.b32 %0, [%1];"
                        : "=r"(bfr[j][half]) : "r"(Bb + bswz(n, q * 2 + half) + lq * 4));
                }
            }
#pragma unroll
            for (int mt = 0; mt < 2; mt++)
#pragma unroll
                for (int j = 0; j < 4; j++)
                    mma_bf16(acc[mt][j], afr[mt], bfr[j]);
        }

        if (g + 2 < e) {
            int pn = pb + 2; if (pn >= 3) pn -= 3;
            issueA(g + 2, pn);
        }
        CP_COMMIT();

        // ---- tile boundary or range end: flush partial R ----
        if ((g + 1 == e) || ((g + 1) % NCHUNK == 0)) {
            int m = g / NCHUNK;
            __syncthreads();
#pragma unroll
            for (int mt = 0; mt < 2; mt++) {
#pragma unroll
                for (int j = 0; j < 4; j++) {
                    int r0  = wm * 32 + mt * 16 + lrow;
                    int col = wn * 32 + j * 8 + lq * 2;
                    uint32_t a0 = sb + SM_T1 + (uint32_t)((r0 * T1_STRIDE + col) * 4);
                    uint32_t a1 = sb + SM_T1 + (uint32_t)(((r0 + 8) * T1_STRIDE + col) * 4);
                    asm volatile("st.shared.v2.f32 [%0], {%1,%2};"
                                 :: "r"(a0), "f"(acc[mt][j][0]), "f"(acc[mt][j][1]));
                    asm volatile("st.shared.v2.f32 [%0], {%1,%2};"
                                 :: "r"(a1), "f"(acc[mt][j][2]), "f"(acc[mt][j][3]));
                }
            }
            __syncthreads();
            if (tid < 256) {
                int fl = tid >> 7;
                int n  = tid & 127;
                float sum = 0.0f;
#pragma unroll 16
                for (int c2 = 0; c2 < 64; c2++)
                    sum += Tsm[(fl * 64 + c2) * T1_STRIDE + n] * __ldg(&wc[c2 * N_ + n]);
                int ord = (s > m * NCHUNK) ? 1 : 0;
                int f2 = m * 2 + fl;
                int b2 = f2 / T_;
                int t2 = f2 - b2 * T_;
                g_R2[(size_t)(ord * 512 + b2 * 128 + n) * T_ + t2] = sum;
                // sole writer of this tile -> ord-1 slot never written: zero it
                if (ord == 0 && e >= (m + 1) * NCHUNK)
                    g_R2[(size_t)(512 + b2 * 128 + n) * T_ + t2] = 0.0f;
            }
#pragma unroll
            for (int mt = 0; mt < 2; mt++)
#pragma unroll
                for (int j = 0; j < 4; j++)
#pragma unroll
                    for (int q = 0; q < 4; q++) acc[mt][j][q] = 0.0f;
        }

        if (++pb >= 3) pb = 0;
    }
}

// ---------------------------------------------------------------------------
// temporal conv: one warp per (b, n) row; coalesced t-contiguous reads
// ---------------------------------------------------------------------------
__global__ void conv_kernel(const float* __restrict__ wt, const float* __restrict__ wb,
                            float* __restrict__ out) {
    __shared__ float rr[8][80];
    __shared__ float wts[8][10];
    int wid = threadIdx.x >> 5, lane = threadIdx.x & 31;
    int row = blockIdx.x * 8 + wid;        // row = b*N + n
    int n = row & 127;
    if (lane < 10) wts[wid][lane] = wt[lane * N_ + n];
    const float* r0 = g_R2 + (size_t)row * T_;
    const float* r1 = g_R2 + (size_t)(512 + row) * T_;
    rr[wid][lane]      = r0[lane]      + r1[lane];
    rr[wid][lane + 32] = r0[lane + 32] + r1[lane + 32];
    if (lane < 16) rr[wid][lane + 64] = r0[lane + 64] + r1[lane + 64];
    __syncwarp();
    float bias = wb[n];
    for (int t0 = lane; t0 < TOUT_; t0 += 32) {
        float sum = bias;
#pragma unroll
        for (int k = 0; k < NT_; k++) sum += rr[wid][t0 + k] * wts[wid][k];
        out[(size_t)row * TOUT_ + t0] = sum;
    }
}

// ---------------------------------------------------------------------------
extern "C" void kernel_launch(void* const* d_in, const int* in_sizes, int n_in,
                              void* d_out, int out_size) {
    (void)in_sizes; (void)n_in; (void)out_size;
    const float* x   = (const float*)d_in[0];
    const float* wc  = (const float*)d_in[2];
    const float* wx  = (const float*)d_in[3];
    const float* wy  = (const float*)d_in[4];
    const float* wsx = (const float*)d_in[5];
    const float* wsy = (const float*)d_in[6];
    const float* wt  = (const float*)d_in[7];
    const float* wb  = (const float*)d_in[8];
    float* out = (float*)d_out;

    cudaFuncSetAttribute(gemm_kernel, cudaFuncAttributeMaxDynamicSharedMemorySize, SMEM_SZ);

    gemm_kernel<<<GRID_G, 512, SMEM_SZ>>>(x, wc, wx, wy, wsx, wsy);
    conv_kernel<<<(B_ * N_) / 8, 256>>>(wt, wb, out);
}